// round 12
// baseline (speedup 1.0000x reference)
#include <cuda_runtime.h>
#include <cuda_bf16.h>
#include <math.h>
#include <stdint.h>

// Problem constants
#define NND   65536      // N nodes
#define DD    256        // feature dim
#define NSS   512        // edge slots
#define EPS_LN   1e-5f
#define EPS_ATTN 1e-8f

// Output layout: [x_out (N*D)] [H (N*NS)] [dots2 (N*NS)]
#define OFF_H   ((size_t)NND * DD)
#define OFF_D2  (OFF_H + (size_t)NND * NSS)

// ------------------------- device scratch (no allocations allowed) -------
__device__ float g_xin[(size_t)NND * DD];          // 64 MB  LN(x)
__device__ float g_qkv[(size_t)NND * 3 * DD];      // 192 MB [q2 | kk | vv] row stride 768
__device__ float g_dots[(size_t)NSS * NND];        // 128 MB edge->node logits
__device__ float g_eln[NSS * DD];
__device__ float g_qe[NSS * DD];
__device__ float g_e2cat[NSS * 2 * DD];            // [e_ln | updates]
__device__ float g_hmlp[NSS * DD];
__device__ float g_enew[NSS * DD];
__device__ float g_k2[NSS * DD];
__device__ float g_eout[NSS * DD];
__device__ float g_wcatT[3 * DD * DD];             // [768][256]: row j = column j of (Wq|Wk|Wv)
__device__ float g_bcat[3 * DD];

// ------------------------- small helpers ---------------------------------
__device__ __forceinline__ unsigned fkey(float f) {
    unsigned u = __float_as_uint(f);
    return (u & 0x80000000u) ? ~u : (u | 0x80000000u); // order-preserving map
}
__device__ __forceinline__ float keyToFloat(unsigned k) {
    unsigned u = (k & 0x80000000u) ? (k & 0x7fffffffu) : ~k;
    return __uint_as_float(u);
}

// 2-way split: x ~= hi + lo, each bf16. hw/lw get {x,y} packed as bf16x2.
__device__ __forceinline__ void cvt2(float x, float y, uint32_t& hw, uint32_t& lw) {
    __nv_bfloat16 hx = __float2bfloat16(x);
    __nv_bfloat16 hy = __float2bfloat16(y);
    __nv_bfloat162 H = __halves2bfloat162(hx, hy);
    __nv_bfloat162 L = __floats2bfloat162_rn(x - __bfloat162float(hx),
                                             y - __bfloat162float(hy));
    hw = *reinterpret_cast<uint32_t*>(&H);
    lw = *reinterpret_cast<uint32_t*>(&L);
}

// 3-way split: x ~= h + m + l (each bf16, ~24 mantissa bits total)
__device__ __forceinline__ void cvt3(float x, float y,
                                     uint32_t& hw, uint32_t& mw, uint32_t& lw) {
    __nv_bfloat16 hx = __float2bfloat16(x);
    __nv_bfloat16 hy = __float2bfloat16(y);
    float rx = x - __bfloat162float(hx);
    float ry = y - __bfloat162float(hy);
    __nv_bfloat16 mx = __float2bfloat16(rx);
    __nv_bfloat16 my = __float2bfloat16(ry);
    float sx = rx - __bfloat162float(mx);
    float sy = ry - __bfloat162float(my);
    __nv_bfloat162 H = __halves2bfloat162(hx, hy);
    __nv_bfloat162 M = __halves2bfloat162(mx, my);
    __nv_bfloat162 L = __floats2bfloat162_rn(sx, sy);
    hw = *reinterpret_cast<uint32_t*>(&H);
    mw = *reinterpret_cast<uint32_t*>(&M);
    lw = *reinterpret_cast<uint32_t*>(&L);
}

__device__ __forceinline__ void mma16816(float* d, const uint32_t* a, const uint32_t* b) {
    asm volatile(
        "mma.sync.aligned.m16n8k16.row.col.f32.bf16.bf16.f32 "
        "{%0,%1,%2,%3}, {%4,%5,%6,%7}, {%8,%9}, {%0,%1,%2,%3};\n"
        : "+f"(d[0]), "+f"(d[1]), "+f"(d[2]), "+f"(d[3])
        : "r"(a[0]), "r"(a[1]), "r"(a[2]), "r"(a[3]), "r"(b[0]), "r"(b[1]));
}

// ------------------------- weight prep -----------------------------------
__global__ void prep_wcat(const float* __restrict__ Wq, const float* __restrict__ bq,
                          const float* __restrict__ Wk, const float* __restrict__ bk,
                          const float* __restrict__ Wv, const float* __restrict__ bv) {
    int idx = blockIdx.x * 256 + threadIdx.x;     // 768*256 total
    int j = idx >> 8, k = idx & 255;
    const float* W = (j < 256) ? Wq : ((j < 512) ? Wk : Wv);
    int jj = j & 255;
    g_wcatT[idx] = W[k * 256 + jj];
    if (k == 0) {
        const float* bb = (j < 256) ? bq : ((j < 512) ? bk : bv);
        g_bcat[j] = bb[jj];
    }
}

// ------------------------- row LayerNorm (nodes) --------------------------
__global__ void node_ln(const float* __restrict__ x, const float* __restrict__ g,
                        const float* __restrict__ b) {
    int row = blockIdx.x, t = threadIdx.x;   // 256 threads
    __shared__ float red[256];
    float v = x[(size_t)row * DD + t];
    red[t] = v; __syncthreads();
    for (int s = 128; s > 0; s >>= 1) { if (t < s) red[t] += red[t + s]; __syncthreads(); }
    float mean = red[0] * (1.0f / DD);
    __syncthreads();
    float d = v - mean;
    red[t] = d * d; __syncthreads();
    for (int s = 128; s > 0; s >>= 1) { if (t < s) red[t] += red[t + s]; __syncthreads(); }
    float var = red[0] * (1.0f / DD);
    g_xin[(size_t)row * DD + t] = d * rsqrtf(var + EPS_LN) * g[t] + b[t];
}

// ------------------------- edge prep: sample + LN -------------------------
__global__ void edge_prep(const float* __restrict__ noise, const float* __restrict__ mu,
                          const float* __restrict__ ls, const float* __restrict__ g,
                          const float* __restrict__ b) {
    int row = blockIdx.x, t = threadIdx.x;   // 512 blocks x 256 threads
    __shared__ float red[256];
    float v = mu[t] + expf(ls[t]) * noise[row * DD + t];
    red[t] = v; __syncthreads();
    for (int s = 128; s > 0; s >>= 1) { if (t < s) red[t] += red[t + s]; __syncthreads(); }
    float mean = red[0] * (1.0f / DD);
    __syncthreads();
    float d = v - mean;
    red[t] = d * d; __syncthreads();
    for (int s = 128; s > 0; s >>= 1) { if (t < s) red[t] += red[t + s]; __syncthreads(); }
    float var = red[0] * (1.0f / DD);
    float o = d * rsqrtf(var + EPS_LN) * g[t] + b[t];
    g_eln[row * DD + t] = o;
    g_e2cat[row * 2 * DD + t] = o;
}

// ------------- small dense: one row per block, 256 output cols ------------
__global__ void rowgemm(const float* __restrict__ X, int ldx, int K,
                        const float* __restrict__ Wm, const float* __restrict__ bias,
                        float* __restrict__ Y, int ldy, int relu) {
    __shared__ float xr[512];
    int row = blockIdx.x, t = threadIdx.x;
    for (int i = t; i < K; i += 256) xr[i] = X[(size_t)row * ldx + i];
    __syncthreads();
    float acc = bias[t];
    for (int k = 0; k < K; k++) acc = fmaf(xr[k], Wm[k * 256 + t], acc);
    if (relu) acc = fmaxf(acc, 0.0f);
    Y[(size_t)row * ldy + t] = acc;
}

// ------------------------- big SGEMM (exact fp32, round-10) ---------------
// C = scale*A*B^T (+bias, relu). 128x128x16, double-buffered, 256 threads.
__global__ void __launch_bounds__(256, 2) sgemm_nt(
        const float* __restrict__ A, int lda,
        const float* __restrict__ B, int ldb,
        float* __restrict__ C, int ldc, int K,
        const float* __restrict__ bias, float scale, int relu_from) {
    __shared__ float As[2][16][132];
    __shared__ float Bs[2][16][132];
    const int tid = threadIdx.x;
    const int bm = blockIdx.y * 128, bn = blockIdx.x * 128;
    const int tx = tid & 15, ty = tid >> 4;
    const int lr = tid & 127;
    const int lk = (tid >> 7) * 8;
    const float* Ag = A + (size_t)(bm + lr) * lda + lk;
    const float* Bg = B + (size_t)(bn + lr) * ldb + lk;

    float acc[8][8] = {};
    float4 a0 = *(const float4*)(Ag);
    float4 a1 = *(const float4*)(Ag + 4);
    float4 b0 = *(const float4*)(Bg);
    float4 b1 = *(const float4*)(Bg + 4);
    As[0][lk + 0][lr] = a0.x; As[0][lk + 1][lr] = a0.y;
    As[0][lk + 2][lr] = a0.z; As[0][lk + 3][lr] = a0.w;
    As[0][lk + 4][lr] = a1.x; As[0][lk + 5][lr] = a1.y;
    As[0][lk + 6][lr] = a1.z; As[0][lk + 7][lr] = a1.w;
    Bs[0][lk + 0][lr] = b0.x; Bs[0][lk + 1][lr] = b0.y;
    Bs[0][lk + 2][lr] = b0.z; Bs[0][lk + 3][lr] = b0.w;
    Bs[0][lk + 4][lr] = b1.x; Bs[0][lk + 5][lr] = b1.y;
    Bs[0][lk + 6][lr] = b1.z; Bs[0][lk + 7][lr] = b1.w;
    __syncthreads();

    const int nIter = K >> 4;
    for (int it = 0; it < nIter; it++) {
        const int cur = it & 1;
        if (it + 1 < nIter) {
            int k0 = (it + 1) << 4;
            a0 = *(const float4*)(Ag + k0);
            a1 = *(const float4*)(Ag + k0 + 4);
            b0 = *(const float4*)(Bg + k0);
            b1 = *(const float4*)(Bg + k0 + 4);
        }
#pragma unroll
        for (int kk = 0; kk < 16; kk++) {
            float a[8], b[8];
            *(float4*)(a)     = *(const float4*)&As[cur][kk][ty * 4];
            *(float4*)(a + 4) = *(const float4*)&As[cur][kk][64 + ty * 4];
            *(float4*)(b)     = *(const float4*)&Bs[cur][kk][tx * 4];
            *(float4*)(b + 4) = *(const float4*)&Bs[cur][kk][64 + tx * 4];
#pragma unroll
            for (int i = 0; i < 8; i++)
#pragma unroll
                for (int j = 0; j < 8; j++)
                    acc[i][j] = fmaf(a[i], b[j], acc[i][j]);
        }
        if (it + 1 < nIter) {
            const int nxt = cur ^ 1;
            As[nxt][lk + 0][lr] = a0.x; As[nxt][lk + 1][lr] = a0.y;
            As[nxt][lk + 2][lr] = a0.z; As[nxt][lk + 3][lr] = a0.w;
            As[nxt][lk + 4][lr] = a1.x; As[nxt][lk + 5][lr] = a1.y;
            As[nxt][lk + 6][lr] = a1.z; As[nxt][lk + 7][lr] = a1.w;
            Bs[nxt][lk + 0][lr] = b0.x; Bs[nxt][lk + 1][lr] = b0.y;
            Bs[nxt][lk + 2][lr] = b0.z; Bs[nxt][lk + 3][lr] = b0.w;
            Bs[nxt][lk + 4][lr] = b1.x; Bs[nxt][lk + 5][lr] = b1.y;
            Bs[nxt][lk + 6][lr] = b1.z; Bs[nxt][lk + 7][lr] = b1.w;
            __syncthreads();
        }
    }
#pragma unroll
    for (int ih = 0; ih < 2; ih++) {
#pragma unroll
        for (int i = 0; i < 4; i++) {
            int row = bm + ih * 64 + ty * 4 + i;
#pragma unroll
            for (int jh = 0; jh < 2; jh++) {
                int col = bn + jh * 64 + tx * 4;
                float4 v;
                float* vp = (float*)&v;
#pragma unroll
                for (int j = 0; j < 4; j++) {
                    float t = acc[ih * 4 + i][jh * 4 + j] * scale;
                    if (bias) t += bias[col + j];
                    if (col + j >= relu_from) t = fmaxf(t, 0.0f);
                    vp[j] = t;
                }
                *(float4*)&C[(size_t)row * ldc + col] = v;
            }
        }
    }
}

// ------- tensor GEMM 3-term (2-way split, ~1e-5 accuracy) -----------------
__global__ void __launch_bounds__(256) tgemm3_nt(
        const float* __restrict__ A, int lda,
        const float* __restrict__ B, int ldb,
        float* __restrict__ C, int ldc, int K,
        const float* __restrict__ bias, float scale, int relu_from) {
    __shared__ uint32_t Ah[128 * 20], Al[128 * 20], Bh[128 * 20], Bl[128 * 20];
    const int tid = threadIdx.x;
    const int bm = blockIdx.y * 128, bn = blockIdx.x * 128;
    const int lane = tid & 31, wid = tid >> 5;
    const int wm = (wid & 1) * 64, wn = (wid >> 1) * 32;
    const int g = lane >> 2, q = lane & 3;

    float acc[4][4][4];
#pragma unroll
    for (int i = 0; i < 4; i++)
#pragma unroll
        for (int j = 0; j < 4; j++)
#pragma unroll
            for (int r = 0; r < 4; r++) acc[i][j][r] = 0.0f;

    const int lrow = tid >> 3;
    const int lkv  = tid & 7;
    const float* Agp = A + (size_t)(bm + lrow) * lda + lkv * 4;
    const float* Bgp = B + (size_t)(bn + lrow) * ldb + lkv * 4;
    const int soff = lrow * 20 + lkv * 2;

    float4 pa[4], pb[4];
    const int nchunk = K >> 5;
#pragma unroll
    for (int i = 0; i < 4; i++) {
        pa[i] = *(const float4*)(Agp + (size_t)i * 32 * lda);
        pb[i] = *(const float4*)(Bgp + (size_t)i * 32 * ldb);
    }
#pragma unroll
    for (int i = 0; i < 4; i++) {
        uint32_t h0, l0, h1, l1;
        int o = soff + i * 640;
        cvt2(pa[i].x, pa[i].y, h0, l0); cvt2(pa[i].z, pa[i].w, h1, l1);
        Ah[o] = h0; Ah[o + 1] = h1; Al[o] = l0; Al[o + 1] = l1;
        cvt2(pb[i].x, pb[i].y, h0, l0); cvt2(pb[i].z, pb[i].w, h1, l1);
        Bh[o] = h0; Bh[o + 1] = h1; Bl[o] = l0; Bl[o + 1] = l1;
    }
    __syncthreads();

    for (int c = 0; c < nchunk; c++) {
        if (c + 1 < nchunk) {
            int k0 = (c + 1) * 32;
#pragma unroll
            for (int i = 0; i < 4; i++) {
                pa[i] = *(const float4*)(Agp + (size_t)i * 32 * lda + k0);
                pb[i] = *(const float4*)(Bgp + (size_t)i * 32 * ldb + k0);
            }
        }
#pragma unroll
        for (int kk = 0; kk < 2; kk++) {
            const int kw = kk * 8 + q;
            uint32_t ah[4][4], al[4][4], bh[4][2], bl[4][2];
#pragma unroll
            for (int i = 0; i < 4; i++) {
                int r0 = (wm + i * 16 + g) * 20;
                ah[i][0] = Ah[r0 + kw];           al[i][0] = Al[r0 + kw];
                ah[i][1] = Ah[r0 + 160 + kw];     al[i][1] = Al[r0 + 160 + kw];
                ah[i][2] = Ah[r0 + kw + 4];       al[i][2] = Al[r0 + kw + 4];
                ah[i][3] = Ah[r0 + 160 + kw + 4]; al[i][3] = Al[r0 + 160 + kw + 4];
            }
#pragma unroll
            for (int j = 0; j < 4; j++) {
                int n0 = (wn + j * 8 + g) * 20;
                bh[j][0] = Bh[n0 + kw]; bh[j][1] = Bh[n0 + kw + 4];
                bl[j][0] = Bl[n0 + kw]; bl[j][1] = Bl[n0 + kw + 4];
            }
#pragma unroll
            for (int i = 0; i < 4; i++)
#pragma unroll
                for (int j = 0; j < 4; j++) {
                    mma16816(acc[i][j], ah[i], bh[j]);
                    mma16816(acc[i][j], ah[i], bl[j]);
                    mma16816(acc[i][j], al[i], bh[j]);
                }
        }
        __syncthreads();
        if (c + 1 < nchunk) {
#pragma unroll
            for (int i = 0; i < 4; i++) {
                uint32_t h0, l0, h1, l1;
                int o = soff + i * 640;
                cvt2(pa[i].x, pa[i].y, h0, l0); cvt2(pa[i].z, pa[i].w, h1, l1);
                Ah[o] = h0; Ah[o + 1] = h1; Al[o] = l0; Al[o + 1] = l1;
                cvt2(pb[i].x, pb[i].y, h0, l0); cvt2(pb[i].z, pb[i].w, h1, l1);
                Bh[o] = h0; Bh[o + 1] = h1; Bl[o] = l0; Bl[o + 1] = l1;
            }
            __syncthreads();
        }
    }
#pragma unroll
    for (int i = 0; i < 4; i++) {
        int row0 = bm + wm + i * 16 + g;
#pragma unroll
        for (int j = 0; j < 4; j++) {
            int col = bn + wn + j * 8 + q * 2;
            float b0 = 0.0f, b1 = 0.0f;
            if (bias) { b0 = bias[col]; b1 = bias[col + 1]; }
            float v0 = acc[i][j][0] * scale + b0;
            float v1 = acc[i][j][1] * scale + b1;
            float v2 = acc[i][j][2] * scale + b0;
            float v3 = acc[i][j][3] * scale + b1;
            if (col >= relu_from)     { v0 = fmaxf(v0, 0.0f); v2 = fmaxf(v2, 0.0f); }
            if (col + 1 >= relu_from) { v1 = fmaxf(v1, 0.0f); v3 = fmaxf(v3, 0.0f); }
            *(float2*)&C[(size_t)row0 * ldc + col] = make_float2(v0, v1);
            *(float2*)&C[(size_t)(row0 + 8) * ldc + col] = make_float2(v2, v3);
        }
    }
}

// ------- tensor GEMM 6-term (3-way split, ~1e-6 accuracy) -----------------
__global__ void __launch_bounds__(256) tgemm6_nt(
        const float* __restrict__ A, int lda,
        const float* __restrict__ B, int ldb,
        float* __restrict__ C, int ldc, int K,
        const float* __restrict__ bias, float scale, int relu_from) {
    extern __shared__ uint32_t smw[];
    uint32_t* Ah = smw;
    uint32_t* Am = smw + 2560;
    uint32_t* Al = smw + 5120;
    uint32_t* Bh = smw + 7680;
    uint32_t* Bm = smw + 10240;
    uint32_t* Bl = smw + 12800;

    const int tid = threadIdx.x;
    const int bm = blockIdx.y * 128, bn = blockIdx.x * 128;
    const int lane = tid & 31, wid = tid >> 5;
    const int wm = (wid & 1) * 64, wn = (wid >> 1) * 32;
    const int g = lane >> 2, q = lane & 3;

    float acc[4][4][4];
#pragma unroll
    for (int i = 0; i < 4; i++)
#pragma unroll
        for (int j = 0; j < 4; j++)
#pragma unroll
            for (int r = 0; r < 4; r++) acc[i][j][r] = 0.0f;

    const int lrow = tid >> 3;
    const int lkv  = tid & 7;
    const float* Agp = A + (size_t)(bm + lrow) * lda + lkv * 4;
    const float* Bgp = B + (size_t)(bn + lrow) * ldb + lkv * 4;
    const int soff = lrow * 20 + lkv * 2;

    float4 pa[4], pb[4];
    const int nchunk = K >> 5;
#pragma unroll
    for (int i = 0; i < 4; i++) {
        pa[i] = *(const float4*)(Agp + (size_t)i * 32 * lda);
        pb[i] = *(const float4*)(Bgp + (size_t)i * 32 * ldb);
    }
#pragma unroll
    for (int i = 0; i < 4; i++) {
        uint32_t h0, m0, l0, h1, m1, l1;
        int o = soff + i * 640;
        cvt3(pa[i].x, pa[i].y, h0, m0, l0); cvt3(pa[i].z, pa[i].w, h1, m1, l1);
        Ah[o] = h0; Ah[o + 1] = h1; Am[o] = m0; Am[o + 1] = m1; Al[o] = l0; Al[o + 1] = l1;
        cvt3(pb[i].x, pb[i].y, h0, m0, l0); cvt3(pb[i].z, pb[i].w, h1, m1, l1);
        Bh[o] = h0; Bh[o + 1] = h1; Bm[o] = m0; Bm[o + 1] = m1; Bl[o] = l0; Bl[o + 1] = l1;
    }
    __syncthreads();

    for (int c = 0; c < nchunk; c++) {
        if (c + 1 < nchunk) {
            int k0 = (c + 1) * 32;
#pragma unroll
            for (int i = 0; i < 4; i++) {
                pa[i] = *(const float4*)(Agp + (size_t)i * 32 * lda + k0);
                pb[i] = *(const float4*)(Bgp + (size_t)i * 32 * ldb + k0);
            }
        }
#pragma unroll
        for (int kk = 0; kk < 2; kk++) {
            const int kw = kk * 8 + q;
            uint32_t bh[4][2], bmf[4][2], blf[4][2];
#pragma unroll
            for (int j = 0; j < 4; j++) {
                int n0 = (wn + j * 8 + g) * 20;
                bh[j][0]  = Bh[n0 + kw]; bh[j][1]  = Bh[n0 + kw + 4];
                bmf[j][0] = Bm[n0 + kw]; bmf[j][1] = Bm[n0 + kw + 4];
                blf[j][0] = Bl[n0 + kw]; blf[j][1] = Bl[n0 + kw + 4];
            }
#pragma unroll
            for (int i = 0; i < 4; i++) {
                int r0 = (wm + i * 16 + g) * 20;
                uint32_t ah[4], am[4], al[4];
                ah[0] = Ah[r0 + kw];           am[0] = Am[r0 + kw];           al[0] = Al[r0 + kw];
                ah[1] = Ah[r0 + 160 + kw];     am[1] = Am[r0 + 160 + kw];     al[1] = Al[r0 + 160 + kw];
                ah[2] = Ah[r0 + kw + 4];       am[2] = Am[r0 + kw + 4];       al[2] = Al[r0 + kw + 4];
                ah[3] = Ah[r0 + 160 + kw + 4]; am[3] = Am[r0 + 160 + kw + 4]; al[3] = Al[r0 + 160 + kw + 4];
#pragma unroll
                for (int j = 0; j < 4; j++) {
                    mma16816(acc[i][j], ah, bh[j]);
                    mma16816(acc[i][j], ah, bmf[j]);
                    mma16816(acc[i][j], am, bh[j]);
                    mma16816(acc[i][j], ah, blf[j]);
                    mma16816(acc[i][j], al, bh[j]);
                    mma16816(acc[i][j], am, bmf[j]);
                }
            }
        }
        __syncthreads();
        if (c + 1 < nchunk) {
#pragma unroll
            for (int i = 0; i < 4; i++) {
                uint32_t h0, m0, l0, h1, m1, l1;
                int o = soff + i * 640;
                cvt3(pa[i].x, pa[i].y, h0, m0, l0); cvt3(pa[i].z, pa[i].w, h1, m1, l1);
                Ah[o] = h0; Ah[o + 1] = h1; Am[o] = m0; Am[o + 1] = m1; Al[o] = l0; Al[o + 1] = l1;
                cvt3(pb[i].x, pb[i].y, h0, m0, l0); cvt3(pb[i].z, pb[i].w, h1, m1, l1);
                Bh[o] = h0; Bh[o + 1] = h1; Bm[o] = m0; Bm[o + 1] = m1; Bl[o] = l0; Bl[o + 1] = l1;
            }
            __syncthreads();
        }
    }
#pragma unroll
    for (int i = 0; i < 4; i++) {
        int row0 = bm + wm + i * 16 + g;
#pragma unroll
        for (int j = 0; j < 4; j++) {
            int col = bn + wn + j * 8 + q * 2;
            float b0 = 0.0f, b1 = 0.0f;
            if (bias) { b0 = bias[col]; b1 = bias[col + 1]; }
            float v0 = acc[i][j][0] * scale + b0;
            float v1 = acc[i][j][1] * scale + b1;
            float v2 = acc[i][j][2] * scale + b0;
            float v3 = acc[i][j][3] * scale + b1;
            if (col >= relu_from)     { v0 = fmaxf(v0, 0.0f); v2 = fmaxf(v2, 0.0f); }
            if (col + 1 >= relu_from) { v1 = fmaxf(v1, 0.0f); v3 = fmaxf(v3, 0.0f); }
            *(float2*)&C[(size_t)row0 * ldc + col] = make_float2(v0, v1);
            *(float2*)&C[(size_t)(row0 + 8) * ldc + col] = make_float2(v2, v3);
        }
    }
}

// ----- edge-side: softmax stats + guarded exact top-k_n + gather ----------
// dots row is tensor-computed (eps ~1e-6). Radix-find approx k-th key, widen
// by DELTA_E, exact-recompute candidates from exact qe/kk (sequential k),
// select by pairwise rank with index tie-break (== jax top_k).
#define DELTA_E 1e-3f
__global__ void __launch_bounds__(1024) edge_select(const int* __restrict__ kn_ptr) {
    const int row = blockIdx.x;
    const int t = threadIdx.x;                    // 1024 threads
    const float* dr = g_dots + (size_t)row * NND;
    __shared__ float red[1024];
    __shared__ unsigned hist[2048];
    __shared__ unsigned sb_bin;
    __shared__ int sb_rem;

    // pass 0 (fused): online max / sum-exp  +  histogram of bits [31:21)
    for (int i = t; i < 2048; i += 1024) hist[i] = 0;
    __syncthreads();
    float m = -3.0e38f, s = 0.0f;
    for (int i = t; i < NND; i += 1024) {
        float dv = dr[i];
        if (dv > m) { s = s * expf(m - dv) + 1.0f; m = dv; }
        else        { s += expf(dv - m); }
        atomicAdd(&hist[fkey(dv) >> 21], 1u);
    }
    red[t] = m; __syncthreads();
    for (int st = 512; st > 0; st >>= 1) { if (t < st) red[t] = fmaxf(red[t], red[t + st]); __syncthreads(); }
    float M = red[0]; __syncthreads();
    red[t] = s * expf(m - M); __syncthreads();
    for (int st = 512; st > 0; st >>= 1) { if (t < st) red[t] += red[t + st]; __syncthreads(); }
    float Z = red[0]; __syncthreads();

    int kq = *kn_ptr;
    unsigned pref = 0, pmask = 0;
    int rem = kq;
    if (t == 0) {
        int cum = 0, b = 2047;
        for (; b >= 0; b--) { cum += (int)hist[b]; if (cum >= rem) break; }
        if (b < 0) b = 0;
        sb_bin = (unsigned)b;
        sb_rem = rem - (cum - (int)hist[b]);
    }
    __syncthreads();
    pref = sb_bin << 21;
    pmask = 2047u << 21;
    rem = sb_rem;
    __syncthreads();

    const int shifts[2] = {10, 0};
    const int bcnts[2]  = {2048, 1024};
    for (int p = 0; p < 2; p++) {
        int bc = bcnts[p], sh = shifts[p];
        for (int i = t; i < bc; i += 1024) hist[i] = 0;
        __syncthreads();
        for (int i = t; i < NND; i += 1024) {
            unsigned key = fkey(dr[i]);
            if ((key & pmask) == pref) atomicAdd(&hist[(key >> sh) & (bc - 1)], 1u);
        }
        __syncthreads();
        if (t == 0) {
            int cum = 0, b = bc - 1;
            for (; b >= 0; b--) { cum += (int)hist[b]; if (cum >= rem) break; }
            if (b < 0) b = 0;
            sb_bin = (unsigned)b;
            sb_rem = rem - (cum - (int)hist[b]);
        }
        __syncthreads();
        pref |= sb_bin << sh;
        pmask |= (unsigned)(bc - 1) << sh;
        rem = sb_rem;
        __syncthreads();
    }

    // widened candidate collection: key >= fkey(T - DELTA_E)
    __shared__ int cnt;
    __shared__ int sidx[256];
    if (t == 0) cnt = 0;
    __syncthreads();
    unsigned klow = fkey(keyToFloat(pref) - DELTA_E);
    for (int i = t; i < NND; i += 1024) {
        if (fkey(dr[i]) >= klow) {
            int p = atomicAdd(&cnt, 1);
            if (p < 256) sidx[p] = i;
        }
    }
    __syncthreads();
    int nc = cnt < 256 ? cnt : 256;

    // exact recompute of candidate dots from exact qe / kk (sequential k)
    __shared__ float qs[256];
    if (t < 256) qs[t] = g_qe[row * DD + t];
    __syncthreads();
    __shared__ float dex[256];
    if (t < nc) {
        const float* kkp = g_qkv + (size_t)sidx[t] * 768 + 256;
        float acc = 0.0f;
#pragma unroll 8
        for (int k = 0; k < 256; k++) acc = fmaf(qs[k], kkp[k], acc);
        dex[t] = acc * 0.0625f;
    }
    __syncthreads();

    // pairwise rank (exact values, lower-index wins ties) -> top-kq
    __shared__ int   selI[128];
    __shared__ float selW[128];
    __shared__ int nsel;
    if (t == 0) nsel = 0;
    __syncthreads();
    const float inv = 1.0f / (1.0f + (float)NND * EPS_ATTN);
    if (t < nc) {
        float dv = dex[t];
        int idx = sidx[t];
        int rank = 0;
        for (int j = 0; j < nc; j++) {
            float dj = dex[j];
            if (dj > dv || (dj == dv && sidx[j] < idx)) rank++;
        }
        if (rank < kq) {
            int p = atomicAdd(&nsel, 1);
            if (p < 128) {
                selI[p] = idx;
                selW[p] = (expf(dv - M) / Z + EPS_ATTN) * inv;
            }
        }
    }
    __syncthreads();
    int nk = nsel < 128 ? nsel : 128;
    if (t < DD) {
        float acc = 0.0f;
        for (int sI = 0; sI < nk; sI++)
            acc = fmaf(selW[sI], g_qkv[(size_t)selI[sI] * 768 + 512 + t], acc);
        g_e2cat[row * 2 * DD + DD + t] = acc;
    }
}

// ----- node-side: softmax(dots2), screened exact top-k_e -> H, x_out ------
// dots2 is tensor-computed. 3-level radix screens an approx top-32 superset;
// candidates' d2 recomputed exactly from exact q2/k2 (sequential k);
// pairwise rank (index tie-break) picks the exact top-k_e.
__global__ void __launch_bounds__(256) node_final(const float* __restrict__ x,
                                                  float* __restrict__ out,
                                                  const int* __restrict__ ke_ptr) {
    int row = blockIdx.x, t = threadIdx.x;  // 256 threads
    const float* d2p = out + OFF_D2 + (size_t)row * NSS;
    __shared__ float d2s[512];
    float d0 = d2p[t], d1 = d2p[t + 256];
    d2s[t] = d0; d2s[t + 256] = d1;
    __shared__ float red[256];
    red[t] = fmaxf(d0, d1); __syncthreads();
    for (int s = 128; s > 0; s >>= 1) { if (t < s) red[t] = fmaxf(red[t], red[t + s]); __syncthreads(); }
    float M = red[0]; __syncthreads();
    float e0 = expf(d0 - M), e1 = expf(d1 - M);
    red[t] = e0 + e1; __syncthreads();
    for (int s = 128; s > 0; s >>= 1) { if (t < s) red[t] += red[t + s]; __syncthreads(); }
    float Z = red[0]; __syncthreads();

    // 3-level radix (8 bits each) to find threshold prefix for rank SCREEN
    const int SCREEN = 32;
    unsigned k0 = fkey(d0), k1 = fkey(d1);
    __shared__ unsigned h8[256];
    __shared__ unsigned sbb; __shared__ int srem;
    unsigned pref = 0, pmask = 0;
    int rem = SCREEN;
#pragma unroll
    for (int lvl = 0; lvl < 3; lvl++) {
        int sh = 24 - lvl * 8;
        h8[t] = 0;
        __syncthreads();
        if ((k0 & pmask) == pref) atomicAdd(&h8[(k0 >> sh) & 255], 1u);
        if ((k1 & pmask) == pref) atomicAdd(&h8[(k1 >> sh) & 255], 1u);
        __syncthreads();
        if (t == 0) {
            int cum = 0, b = 255;
            for (; b >= 0; b--) { cum += (int)h8[b]; if (cum >= rem) break; }
            if (b < 0) b = 0;
            sbb = (unsigned)b;
            srem = rem - (cum - (int)h8[b]);
        }
        __syncthreads();
        pref |= sbb << sh;
        pmask |= 255u << sh;
        rem = srem;
        __syncthreads();
    }

    // collect candidates with key >= pref (cap 64)
    __shared__ int cidx[64];
    __shared__ int ccnt;
    if (t == 0) ccnt = 0;
    __syncthreads();
    if (k0 >= pref) { int p = atomicAdd(&ccnt, 1); if (p < 64) cidx[p] = t; }
    if (k1 >= pref) { int p = atomicAdd(&ccnt, 1); if (p < 64) cidx[p] = t + 256; }
    __syncthreads();
    int nc = ccnt < 64 ? ccnt : 64;

    // exact recompute of candidate d2 from exact q2 (qkv cols 0..255) and k2
    __shared__ float qs[256];
    qs[t] = g_qkv[(size_t)row * 768 + t];
    __syncthreads();
    __shared__ float dex[64];
    if (t < nc) {
        const float* k2p = g_k2 + (size_t)cidx[t] * DD;
        float acc = 0.0f;
#pragma unroll 8
        for (int k = 0; k < 256; k++) acc = fmaf(qs[k], k2p[k], acc);
        dex[t] = acc * 0.0625f;
    }
    __syncthreads();

    // pairwise rank -> top-ke (index tie-break)
    int ke = *ke_ptr;
    __shared__ int selList[16];
    __shared__ int nsel;
    if (t == 0) nsel = 0;
    __syncthreads();
    if (t < nc) {
        float dv = dex[t];
        int ci = cidx[t];
        int rank = 0;
        for (int j = 0; j < nc; j++) {
            float dj = dex[j];
            if (dj > dv || (dj == dv && cidx[j] < ci)) rank++;
        }
        if (rank < ke) {
            int p = atomicAdd(&nsel, 1);
            if (p < 16) selList[p] = ci;
        }
    }
    __syncthreads();
    int ns = nsel < 16 ? nsel : 16;

    __shared__ unsigned char flag[512];
    flag[t] = 0; flag[t + 256] = 0;
    __syncthreads();
    if (t < ns) flag[selList[t]] = 1;
    __syncthreads();

    float sv0 = e0 / Z, sv1 = e1 / Z;
    out[OFF_H + (size_t)row * NSS + t]       = flag[t]       ? sv0 : 0.0f;
    out[OFF_H + (size_t)row * NSS + t + 256] = flag[t + 256] ? sv1 : 0.0f;
    float acc = x[(size_t)row * DD + t];
    for (int sI = 0; sI < ns; sI++) {
        int col = selList[sI];
        float w = expf(d2s[col] - M) / Z;
        acc = fmaf(w, g_eout[col * DD + t], acc);
    }
    out[(size_t)row * DD + t] = acc;
}

// ------------------------- launch ----------------------------------------
extern "C" void kernel_launch(void* const* d_in, const int* in_sizes, int n_in,
                              void* d_out, int out_size) {
    const float* x    = (const float*)d_in[0];
    const float* noise= (const float*)d_in[1];
    const float* emu  = (const float*)d_in[2];
    const float* els  = (const float*)d_in[3];
    const float* lng  = (const float*)d_in[4];
    const float* lnb  = (const float*)d_in[5];
    const float* leg  = (const float*)d_in[6];
    const float* leb  = (const float*)d_in[7];
    const float* Wq = (const float*)d_in[8];  const float* bq = (const float*)d_in[9];
    const float* Wk = (const float*)d_in[10]; const float* bk = (const float*)d_in[11];
    const float* Wv = (const float*)d_in[12]; const float* bv = (const float*)d_in[13];
    const float* W1 = (const float*)d_in[14]; const float* b1 = (const float*)d_in[15];
    const float* W2 = (const float*)d_in[16]; const float* b2 = (const float*)d_in[17];
    const float* W  = (const float*)d_in[18]; const float* b  = (const float*)d_in[19];
    const int* knp  = (const int*)d_in[20];
    const int* kep  = (const int*)d_in[21];
    float* out = (float*)d_out;

    float *p_xin, *p_qkv, *p_dots, *p_qe, *p_k2, *p_eln, *p_e2, *p_h, *p_en, *p_wT, *p_bc, *p_eo;
    cudaGetSymbolAddress((void**)&p_xin, g_xin);
    cudaGetSymbolAddress((void**)&p_qkv, g_qkv);
    cudaGetSymbolAddress((void**)&p_dots, g_dots);
    cudaGetSymbolAddress((void**)&p_qe, g_qe);
    cudaGetSymbolAddress((void**)&p_k2, g_k2);
    cudaGetSymbolAddress((void**)&p_eln, g_eln);
    cudaGetSymbolAddress((void**)&p_e2, g_e2cat);
    cudaGetSymbolAddress((void**)&p_h, g_hmlp);
    cudaGetSymbolAddress((void**)&p_en, g_enew);
    cudaGetSymbolAddress((void**)&p_wT, g_wcatT);
    cudaGetSymbolAddress((void**)&p_bc, g_bcat);
    cudaGetSymbolAddress((void**)&p_eo, g_eout);

    cudaFuncSetAttribute(tgemm6_nt, cudaFuncAttributeMaxDynamicSharedMemorySize, 61440);

    // 1) weight concat/transpose + biases
    prep_wcat<<<768, 256>>>(Wq, bq, Wk, bk, Wv, bv);
    // 2) node LN
    node_ln<<<NND, 256>>>(x, lng, lnb);
    // 3) edge sample + LN
    edge_prep<<<NSS, 256>>>(noise, emu, els, leg, leb);
    // 4) q_e = relu(e_ln @ Wq + bq)  [exact]
    rowgemm<<<NSS, 256>>>(p_eln, DD, DD, Wq, bq, p_qe, DD, 1);
    // 5) qkv exact scalar (selection-critical inputs kk/vv/q2 stay fp32-exact)
    {
        dim3 g(3 * DD / 128, NND / 128);
        sgemm_nt<<<g, 256>>>(p_xin, DD, p_wT, DD, p_qkv, 3 * DD, DD, p_bc, 1.0f, 256);
    }
    // 6) dots = (q_e @ kk^T) * D^-0.5  [tensor 6-term; selection guarded below]
    {
        dim3 g(NND / 128, NSS / 128);
        tgemm6_nt<<<g, 256, 61440>>>(p_qe, DD, p_qkv + 256, 3 * DD, p_dots, NND, DD,
                                     nullptr, 0.0625f, 1 << 30);
    }
    // 7) guarded edge selection + exact candidate recompute + gather
    edge_select<<<NSS, 1024>>>(knp);
    // 8) edge MLP + heads [exact]
    rowgemm<<<NSS, 256>>>(p_e2, 2 * DD, 2 * DD, W1, b1, p_h, DD, 1);
    rowgemm<<<NSS, 256>>>(p_h, DD, DD, W2, b2, p_en, DD, 0);
    rowgemm<<<NSS, 256>>>(p_en, DD, DD, Wk, bk, p_k2, DD, 1);
    rowgemm<<<NSS, 256>>>(p_en, DD, DD, W, b, p_eo, DD, 0);
    // 9) dots2 = (q2 @ k2^T) * D^-0.5 -> output slab  [tensor 3-term]
    {
        dim3 g(NSS / 128, NND / 128);
        tgemm3_nt<<<g, 256>>>(p_qkv, 3 * DD, p_k2, DD, out + OFF_D2, NSS, DD,
                              nullptr, 0.0625f, 1 << 30);
    }
    // 10) screened exact top-k_e -> H + fused residual x_out
    node_final<<<NND, 256>>>(x, out, kep);
}